// round 2
// baseline (speedup 1.0000x reference)
#include <cuda_runtime.h>
#include <math.h>

#define T_SEQ 4096
#define C_MODEL 1024
#define NHEADS 16
#define DHEAD 64

// Scratch (allocation-free rule: __device__ globals)
__device__ float g_q[T_SEQ * C_MODEL];
__device__ float g_k[T_SEQ * C_MODEL];
__device__ float g_v[T_SEQ * C_MODEL];
__device__ float g_attn[T_SEQ * C_MODEL];

// ---------------------------------------------------------------------------
// C[M,N] = A[M,K] @ B[N,K]^T + bias[N]
// 128x128 tile, BK=8, 256 threads, 8x8 microtile per thread.
// Both A and B are K-major (row-major [rows, K]), so the same transposed
// smem-staging works for both operands.
// ---------------------------------------------------------------------------
#define GPITCH 132  // 128 + 4 pad: avoids store-bank conflicts on the transpose

__global__ __launch_bounds__(256) void gemm_bias(
    const float* __restrict__ A, const float* __restrict__ B,
    const float* __restrict__ bias, float* __restrict__ Cout,
    int M, int N, int K) {
  __shared__ float As[8][GPITCH];
  __shared__ float Bs[8][GPITCH];
  const int tid = threadIdx.x;
  const int ty = tid >> 4;        // 0..15
  const int tx = tid & 15;        // 0..15
  const int bm = blockIdx.y * 128;
  const int bn = blockIdx.x * 128;
  const int lrow = tid >> 1;          // 0..127
  const int lcol = (tid & 1) << 2;    // 0 or 4

  float acc[8][8];
#pragma unroll
  for (int i = 0; i < 8; i++)
#pragma unroll
    for (int j = 0; j < 8; j++) acc[i][j] = 0.f;

  const float* Aptr = A + (bm + lrow) * K + lcol;
  const float* Bptr = B + (bn + lrow) * K + lcol;

  for (int k0 = 0; k0 < K; k0 += 8) {
    float4 a4 = *(const float4*)(Aptr + k0);
    float4 b4 = *(const float4*)(Bptr + k0);
    __syncthreads();  // protect smem from previous iteration's readers
    As[lcol + 0][lrow] = a4.x; As[lcol + 1][lrow] = a4.y;
    As[lcol + 2][lrow] = a4.z; As[lcol + 3][lrow] = a4.w;
    Bs[lcol + 0][lrow] = b4.x; Bs[lcol + 1][lrow] = b4.y;
    Bs[lcol + 2][lrow] = b4.z; Bs[lcol + 3][lrow] = b4.w;
    __syncthreads();
#pragma unroll
    for (int k = 0; k < 8; k++) {
      float a[8], b[8];
      *(float4*)&a[0] = *(const float4*)&As[k][ty * 8 + 0];
      *(float4*)&a[4] = *(const float4*)&As[k][ty * 8 + 4];
      *(float4*)&b[0] = *(const float4*)&Bs[k][tx * 8 + 0];
      *(float4*)&b[4] = *(const float4*)&Bs[k][tx * 8 + 4];
#pragma unroll
      for (int i = 0; i < 8; i++)
#pragma unroll
        for (int j = 0; j < 8; j++) acc[i][j] = fmaf(a[i], b[j], acc[i][j]);
    }
  }

#pragma unroll
  for (int i = 0; i < 8; i++) {
    const int r = bm + ty * 8 + i;
#pragma unroll
    for (int j = 0; j < 8; j += 4) {
      const int c = bn + tx * 8 + j;
      float4 o;
      o.x = acc[i][j + 0] + bias[c + 0];
      o.y = acc[i][j + 1] + bias[c + 1];
      o.z = acc[i][j + 2] + bias[c + 2];
      o.w = acc[i][j + 3] + bias[c + 3];
      *(float4*)(Cout + r * N + c) = o;
    }
  }
}

// ---------------------------------------------------------------------------
// Causal flash attention, fp32. One block per (q-tile of 64, head).
// 256 threads; 4x4 microtile over the 64x64 score tile per thread.
// smem pitch 65 floats to keep conflicts <= 2-way.
// ---------------------------------------------------------------------------
#define PITCH 65
#define ATTN_SMEM (4 * 64 * PITCH * sizeof(float))

__global__ __launch_bounds__(256) void flash_attn(
    const float* __restrict__ Q, const float* __restrict__ K,
    const float* __restrict__ V, float* __restrict__ O) {
  extern __shared__ float sm[];
  float* Qs = sm;                  // [64][PITCH]
  float* Ks = Qs + 64 * PITCH;
  float* Vs = Ks + 64 * PITCH;
  float* Ps = Vs + 64 * PITCH;

  const int qt = blockIdx.x;       // q tile index (0..63)
  const int h  = blockIdx.y;       // head
  const int tid = threadIdx.x;
  const int ty = tid >> 4;
  const int tx = tid & 15;
  const float scale = 0.125f;      // 1/sqrt(64)

  // Load Q tile [64 rows][64 dims]
  {
    const int row = tid >> 2;              // 0..63
    const int cbase = (tid & 3) * 16;      // 0,16,32,48
    const float* src = Q + (qt * 64 + row) * C_MODEL + h * DHEAD + cbase;
#pragma unroll
    for (int i = 0; i < 4; i++) {
      float4 v4 = *(const float4*)(src + i * 4);
      float* d = &Qs[row * PITCH + cbase + i * 4];
      d[0] = v4.x; d[1] = v4.y; d[2] = v4.z; d[3] = v4.w;
    }
  }

  float m_i[4], l_i[4], Oacc[4][4];
#pragma unroll
  for (int a = 0; a < 4; a++) {
    m_i[a] = -1e30f; l_i[a] = 0.f;
#pragma unroll
    for (int b = 0; b < 4; b++) Oacc[a][b] = 0.f;
  }

  for (int kt = 0; kt <= qt; kt++) {
    __syncthreads();  // protect Ks/Vs from previous iteration's readers
    {
      const int row = tid >> 2;
      const int cbase = (tid & 3) * 16;
      const float* ksrc = K + (kt * 64 + row) * C_MODEL + h * DHEAD + cbase;
      const float* vsrc = V + (kt * 64 + row) * C_MODEL + h * DHEAD + cbase;
#pragma unroll
      for (int i = 0; i < 4; i++) {
        float4 kv = *(const float4*)(ksrc + i * 4);
        float* kd = &Ks[row * PITCH + cbase + i * 4];
        kd[0] = kv.x; kd[1] = kv.y; kd[2] = kv.z; kd[3] = kv.w;
        float4 vv = *(const float4*)(vsrc + i * 4);
        float* vd = &Vs[row * PITCH + cbase + i * 4];
        vd[0] = vv.x; vd[1] = vv.y; vd[2] = vv.z; vd[3] = vv.w;
      }
    }
    __syncthreads();

    // S = Q K^T for this tile (4x4 per thread)
    float s[4][4];
#pragma unroll
    for (int a = 0; a < 4; a++)
#pragma unroll
      for (int j = 0; j < 4; j++) s[a][j] = 0.f;
    for (int d = 0; d < 64; d++) {
      float a[4], b[4];
#pragma unroll
      for (int i = 0; i < 4; i++) a[i] = Qs[(ty * 4 + i) * PITCH + d];
#pragma unroll
      for (int j = 0; j < 4; j++) b[j] = Ks[(tx * 4 + j) * PITCH + d];
#pragma unroll
      for (int i = 0; i < 4; i++)
#pragma unroll
        for (int j = 0; j < 4; j++) s[i][j] = fmaf(a[i], b[j], s[i][j]);
    }
    // scale + causal mask (only the diagonal tile needs masking)
#pragma unroll
    for (int a = 0; a < 4; a++)
#pragma unroll
      for (int j = 0; j < 4; j++) {
        s[a][j] *= scale;
        if (kt == qt && (tx * 4 + j) > (ty * 4 + a)) s[a][j] = -1e30f;
      }

    // Online softmax update (rows are spread across 16 tx-lanes)
#pragma unroll
    for (int a = 0; a < 4; a++) {
      float rm = s[a][0];
#pragma unroll
      for (int j = 1; j < 4; j++) rm = fmaxf(rm, s[a][j]);
#pragma unroll
      for (int off = 8; off > 0; off >>= 1)
        rm = fmaxf(rm, __shfl_xor_sync(0xffffffffu, rm, off));
      const float mnew = fmaxf(m_i[a], rm);
      const float alpha = __expf(m_i[a] - mnew);
      float rs = 0.f;
#pragma unroll
      for (int j = 0; j < 4; j++) {
        const float p = __expf(s[a][j] - mnew);
        s[a][j] = p;
        rs += p;
      }
#pragma unroll
      for (int off = 8; off > 0; off >>= 1)
        rs += __shfl_xor_sync(0xffffffffu, rs, off);
      l_i[a] = l_i[a] * alpha + rs;
      m_i[a] = mnew;
#pragma unroll
      for (int b = 0; b < 4; b++) Oacc[a][b] *= alpha;
#pragma unroll
      for (int j = 0; j < 4; j++)
        Ps[(ty * 4 + a) * PITCH + tx * 4 + j] = s[a][j];
    }
    __syncthreads();

    // O += P V
    for (int jj = 0; jj < 64; jj++) {
      float p[4], vv[4];
#pragma unroll
      for (int a = 0; a < 4; a++) p[a] = Ps[(ty * 4 + a) * PITCH + jj];
#pragma unroll
      for (int b = 0; b < 4; b++) vv[b] = Vs[jj * PITCH + tx * 4 + b];
#pragma unroll
      for (int a = 0; a < 4; a++)
#pragma unroll
        for (int b = 0; b < 4; b++) Oacc[a][b] = fmaf(p[a], vv[b], Oacc[a][b]);
    }
  }

  // Epilogue: normalize and store into [T, C] with head-interleaved layout
#pragma unroll
  for (int a = 0; a < 4; a++) {
    const float inv = 1.f / l_i[a];
    const int r = qt * 64 + ty * 4 + a;
#pragma unroll
    for (int b = 0; b < 4; b++)
      O[r * C_MODEL + h * DHEAD + tx * 4 + b] = Oacc[a][b] * inv;
  }
}

// ---------------------------------------------------------------------------
extern "C" void kernel_launch(void* const* d_in, const int* in_sizes, int n_in,
                              void* d_out, int out_size) {
  const float* x  = (const float*)d_in[0];
  const float* Wq = (const float*)d_in[1];
  const float* bq = (const float*)d_in[2];
  const float* Wk = (const float*)d_in[3];
  const float* bk = (const float*)d_in[4];
  const float* Wv = (const float*)d_in[5];
  const float* bv = (const float*)d_in[6];
  const float* Wo = (const float*)d_in[7];
  const float* bo = (const float*)d_in[8];
  // d_in[9] = mask, ignored (causality is hard-coded)
  float* out = (float*)d_out;

  float *qp, *kp, *vp, *ap;
  cudaGetSymbolAddress((void**)&qp, g_q);
  cudaGetSymbolAddress((void**)&kp, g_k);
  cudaGetSymbolAddress((void**)&vp, g_v);
  cudaGetSymbolAddress((void**)&ap, g_attn);

  cudaFuncSetAttribute(flash_attn, cudaFuncAttributeMaxDynamicSharedMemorySize,
                       (int)ATTN_SMEM);

  dim3 gb(C_MODEL / 128, T_SEQ / 128);  // (8, 32)
  gemm_bias<<<gb, 256>>>(x, Wq, bq, qp, T_SEQ, C_MODEL, C_MODEL);
  gemm_bias<<<gb, 256>>>(x, Wk, bk, kp, T_SEQ, C_MODEL, C_MODEL);
  gemm_bias<<<gb, 256>>>(x, Wv, bv, vp, T_SEQ, C_MODEL, C_MODEL);

  dim3 ga(T_SEQ / 64, NHEADS);          // (64, 16)
  flash_attn<<<ga, 256, ATTN_SMEM>>>(qp, kp, vp, ap);

  gemm_bias<<<gb, 256>>>(ap, Wo, bo, out, T_SEQ, C_MODEL, C_MODEL);
}

// round 3
// speedup vs baseline: 1.1696x; 1.1696x over previous
#include <cuda_runtime.h>
#include <math.h>

#define T_SEQ 4096
#define C_MODEL 1024
#define NHEADS 16
#define DHEAD 64

// Scratch (allocation-free rule: __device__ globals)
__device__ float g_q[T_SEQ * C_MODEL];
__device__ float g_k[T_SEQ * C_MODEL];
__device__ float g_v[T_SEQ * C_MODEL];
__device__ float g_attn[T_SEQ * C_MODEL];

// ---------------------------------------------------------------------------
// C[M,N] = A[M,K] @ B[N,K]^T + bias[N]
// 128x128 tile, BK=8, 256 threads, 8x8 microtile per thread.
// ---------------------------------------------------------------------------
#define GPITCH 132

__global__ __launch_bounds__(256) void gemm_bias(
    const float* __restrict__ A, const float* __restrict__ B,
    const float* __restrict__ bias, float* __restrict__ Cout,
    int M, int N, int K) {
  __shared__ float As[8][GPITCH];
  __shared__ float Bs[8][GPITCH];
  const int tid = threadIdx.x;
  const int ty = tid >> 4;
  const int tx = tid & 15;
  const int bm = blockIdx.y * 128;
  const int bn = blockIdx.x * 128;
  const int lrow = tid >> 1;
  const int lcol = (tid & 1) << 2;

  float acc[8][8];
#pragma unroll
  for (int i = 0; i < 8; i++)
#pragma unroll
    for (int j = 0; j < 8; j++) acc[i][j] = 0.f;

  const float* Aptr = A + (bm + lrow) * K + lcol;
  const float* Bptr = B + (bn + lrow) * K + lcol;

  for (int k0 = 0; k0 < K; k0 += 8) {
    float4 a4 = *(const float4*)(Aptr + k0);
    float4 b4 = *(const float4*)(Bptr + k0);
    __syncthreads();
    As[lcol + 0][lrow] = a4.x; As[lcol + 1][lrow] = a4.y;
    As[lcol + 2][lrow] = a4.z; As[lcol + 3][lrow] = a4.w;
    Bs[lcol + 0][lrow] = b4.x; Bs[lcol + 1][lrow] = b4.y;
    Bs[lcol + 2][lrow] = b4.z; Bs[lcol + 3][lrow] = b4.w;
    __syncthreads();
#pragma unroll
    for (int k = 0; k < 8; k++) {
      float a[8], b[8];
      *(float4*)&a[0] = *(const float4*)&As[k][ty * 8 + 0];
      *(float4*)&a[4] = *(const float4*)&As[k][ty * 8 + 4];
      *(float4*)&b[0] = *(const float4*)&Bs[k][tx * 8 + 0];
      *(float4*)&b[4] = *(const float4*)&Bs[k][tx * 8 + 4];
#pragma unroll
      for (int i = 0; i < 8; i++)
#pragma unroll
        for (int j = 0; j < 8; j++) acc[i][j] = fmaf(a[i], b[j], acc[i][j]);
    }
  }

#pragma unroll
  for (int i = 0; i < 8; i++) {
    const int r = bm + ty * 8 + i;
#pragma unroll
    for (int j = 0; j < 8; j += 4) {
      const int c = bn + tx * 8 + j;
      float4 o;
      o.x = acc[i][j + 0] + bias[c + 0];
      o.y = acc[i][j + 1] + bias[c + 1];
      o.z = acc[i][j + 2] + bias[c + 2];
      o.w = acc[i][j + 3] + bias[c + 3];
      *(float4*)(Cout + r * N + c) = o;
    }
  }
}

// ---------------------------------------------------------------------------
// Causal flash attention, fp32, gemm-style tiling.
// One block per (head, 128-row q block). 256 threads.
// S tile: 128x128, 8x8 microtile (16x16 thread grid).
// PV: 8 rows x 4 dims per thread.
// Softmax runs in base-2 with scale*log2(e) folded into the scores.
// ---------------------------------------------------------------------------
#define BM 128
#define BN 128
#define AD 64
#define PQ 132   // pitch for Qs/Ks: [AD][BM]
#define PVP 68   // pitch for Vs:   [BN][AD]
#define PP 132   // pitch for Ps:   [BM][BN]

#define ATTN_SMEM ((2 * AD * PQ + BN * PVP + BM * PP) * sizeof(float))

__global__ __launch_bounds__(256) void flash_attn2(
    const float* __restrict__ Q, const float* __restrict__ K,
    const float* __restrict__ V, float* __restrict__ O) {
  extern __shared__ float sm[];
  float* Qs = sm;                  // [AD][PQ]  (transposed: Qs[d][row])
  float* Ks = Qs + AD * PQ;        // [AD][PQ]  (transposed: Ks[d][col])
  float* Vs = Ks + AD * PQ;        // [BN][PVP] (natural: Vs[krow][d])
  float* Ps = Vs + BN * PVP;       // [BM][PP]  (natural: Ps[qrow][kcol])

  const int qb = gridDim.x - 1 - blockIdx.x;  // heavy blocks first
  const int h  = blockIdx.y;
  const int tid = threadIdx.x;
  const int ty = tid >> 4;
  const int tx = tid & 15;
  // softmax in base-2: scores_log2 = (q.k) * (1/sqrt(64)) * log2(e)
  const float scale2 = 0.125f * 1.44269504088896f;

  // Load Q block [128 x 64], transposed into Qs[d][row]
  {
    const int r = tid >> 1;
    const int cb = (tid & 1) * 32;
    const float* src = Q + (qb * BM + r) * C_MODEL + h * AD + cb;
#pragma unroll
    for (int i = 0; i < 8; i++) {
      float4 v4 = *(const float4*)(src + i * 4);
      Qs[(cb + i * 4 + 0) * PQ + r] = v4.x;
      Qs[(cb + i * 4 + 1) * PQ + r] = v4.y;
      Qs[(cb + i * 4 + 2) * PQ + r] = v4.z;
      Qs[(cb + i * 4 + 3) * PQ + r] = v4.w;
    }
  }

  float m_i[8], l_i[8], Oacc[8][4];
#pragma unroll
  for (int a = 0; a < 8; a++) {
    m_i[a] = -1e30f; l_i[a] = 0.f;
#pragma unroll
    for (int c = 0; c < 4; c++) Oacc[a][c] = 0.f;
  }

  for (int kt = 0; kt <= qb; kt++) {
    __syncthreads();  // protect Ks/Vs/Ps from previous iteration's readers
    {
      const int r = tid >> 1;
      const int cb = (tid & 1) * 32;
      const float* ks = K + (kt * BN + r) * C_MODEL + h * AD + cb;
      const float* vs = V + (kt * BN + r) * C_MODEL + h * AD + cb;
#pragma unroll
      for (int i = 0; i < 8; i++) {
        float4 kv = *(const float4*)(ks + i * 4);
        Ks[(cb + i * 4 + 0) * PQ + r] = kv.x;
        Ks[(cb + i * 4 + 1) * PQ + r] = kv.y;
        Ks[(cb + i * 4 + 2) * PQ + r] = kv.z;
        Ks[(cb + i * 4 + 3) * PQ + r] = kv.w;
        *(float4*)&Vs[r * PVP + cb + i * 4] = *(const float4*)(vs + i * 4);
      }
    }
    __syncthreads();

    // ---- S = Q K^T (8x8 per thread) ----
    float s[8][8];
#pragma unroll
    for (int a = 0; a < 8; a++)
#pragma unroll
      for (int j = 0; j < 8; j++) s[a][j] = 0.f;
#pragma unroll 4
    for (int k = 0; k < AD; k++) {
      float a[8], b[8];
      *(float4*)&a[0] = *(const float4*)&Qs[k * PQ + ty * 8 + 0];
      *(float4*)&a[4] = *(const float4*)&Qs[k * PQ + ty * 8 + 4];
      *(float4*)&b[0] = *(const float4*)&Ks[k * PQ + tx * 8 + 0];
      *(float4*)&b[4] = *(const float4*)&Ks[k * PQ + tx * 8 + 4];
#pragma unroll
      for (int i = 0; i < 8; i++)
#pragma unroll
        for (int j = 0; j < 8; j++) s[i][j] = fmaf(a[i], b[j], s[i][j]);
    }

    // scale (log2 domain) + causal mask (diagonal tile only)
    if (kt == qb) {
#pragma unroll
      for (int a = 0; a < 8; a++)
#pragma unroll
        for (int j = 0; j < 8; j++)
          s[a][j] = (tx * 8 + j) > (ty * 8 + a) ? -1e30f : s[a][j] * scale2;
    } else {
#pragma unroll
      for (int a = 0; a < 8; a++)
#pragma unroll
        for (int j = 0; j < 8; j++) s[a][j] *= scale2;
    }

    // ---- online softmax (rows spread across 16 tx lanes) ----
#pragma unroll
    for (int a = 0; a < 8; a++) {
      float rm = s[a][0];
#pragma unroll
      for (int j = 1; j < 8; j++) rm = fmaxf(rm, s[a][j]);
#pragma unroll
      for (int off = 8; off > 0; off >>= 1)
        rm = fmaxf(rm, __shfl_xor_sync(0xffffffffu, rm, off));
      const float mnew = fmaxf(m_i[a], rm);
      const float alpha = exp2f(m_i[a] - mnew);
      float rs = 0.f;
#pragma unroll
      for (int j = 0; j < 8; j++) {
        const float p = exp2f(s[a][j] - mnew);
        s[a][j] = p;
        rs += p;
      }
#pragma unroll
      for (int off = 8; off > 0; off >>= 1)
        rs += __shfl_xor_sync(0xffffffffu, rs, off);
      l_i[a] = l_i[a] * alpha + rs;
      m_i[a] = mnew;
#pragma unroll
      for (int c = 0; c < 4; c++) Oacc[a][c] *= alpha;
      // store P row-major (broadcast-friendly reads in PV)
      float4 p0 = make_float4(s[a][0], s[a][1], s[a][2], s[a][3]);
      float4 p1 = make_float4(s[a][4], s[a][5], s[a][6], s[a][7]);
      *(float4*)&Ps[(ty * 8 + a) * PP + tx * 8 + 0] = p0;
      *(float4*)&Ps[(ty * 8 + a) * PP + tx * 8 + 4] = p1;
    }
    __syncthreads();

    // ---- O += P V (8 rows x 4 dims per thread) ----
#pragma unroll 2
    for (int j0 = 0; j0 < BN; j0 += 4) {
      float4 vr[4];
#pragma unroll
      for (int jj = 0; jj < 4; jj++)
        vr[jj] = *(const float4*)&Vs[(j0 + jj) * PVP + tx * 4];
#pragma unroll
      for (int a = 0; a < 8; a++) {
        float4 p4 = *(const float4*)&Ps[(ty * 8 + a) * PP + j0];
        Oacc[a][0] = fmaf(p4.x, vr[0].x, Oacc[a][0]);
        Oacc[a][1] = fmaf(p4.x, vr[0].y, Oacc[a][1]);
        Oacc[a][2] = fmaf(p4.x, vr[0].z, Oacc[a][2]);
        Oacc[a][3] = fmaf(p4.x, vr[0].w, Oacc[a][3]);
        Oacc[a][0] = fmaf(p4.y, vr[1].x, Oacc[a][0]);
        Oacc[a][1] = fmaf(p4.y, vr[1].y, Oacc[a][1]);
        Oacc[a][2] = fmaf(p4.y, vr[1].z, Oacc[a][2]);
        Oacc[a][3] = fmaf(p4.y, vr[1].w, Oacc[a][3]);
        Oacc[a][0] = fmaf(p4.z, vr[2].x, Oacc[a][0]);
        Oacc[a][1] = fmaf(p4.z, vr[2].y, Oacc[a][1]);
        Oacc[a][2] = fmaf(p4.z, vr[2].z, Oacc[a][2]);
        Oacc[a][3] = fmaf(p4.z, vr[2].w, Oacc[a][3]);
        Oacc[a][0] = fmaf(p4.w, vr[3].x, Oacc[a][0]);
        Oacc[a][1] = fmaf(p4.w, vr[3].y, Oacc[a][1]);
        Oacc[a][2] = fmaf(p4.w, vr[3].z, Oacc[a][2]);
        Oacc[a][3] = fmaf(p4.w, vr[3].w, Oacc[a][3]);
      }
    }
  }

  // Epilogue: normalize and store [T, C] head-interleaved
#pragma unroll
  for (int a = 0; a < 8; a++) {
    const float inv = 1.f / l_i[a];
    const int r = qb * BM + ty * 8 + a;
    float4 o;
    o.x = Oacc[a][0] * inv;
    o.y = Oacc[a][1] * inv;
    o.z = Oacc[a][2] * inv;
    o.w = Oacc[a][3] * inv;
    *(float4*)(O + r * C_MODEL + h * AD + tx * 4) = o;
  }
}

// ---------------------------------------------------------------------------
extern "C" void kernel_launch(void* const* d_in, const int* in_sizes, int n_in,
                              void* d_out, int out_size) {
  const float* x  = (const float*)d_in[0];
  const float* Wq = (const float*)d_in[1];
  const float* bq = (const float*)d_in[2];
  const float* Wk = (const float*)d_in[3];
  const float* bk = (const float*)d_in[4];
  const float* Wv = (const float*)d_in[5];
  const float* bv = (const float*)d_in[6];
  const float* Wo = (const float*)d_in[7];
  const float* bo = (const float*)d_in[8];
  float* out = (float*)d_out;

  float *qp, *kp, *vp, *ap;
  cudaGetSymbolAddress((void**)&qp, g_q);
  cudaGetSymbolAddress((void**)&kp, g_k);
  cudaGetSymbolAddress((void**)&vp, g_v);
  cudaGetSymbolAddress((void**)&ap, g_attn);

  cudaFuncSetAttribute(flash_attn2, cudaFuncAttributeMaxDynamicSharedMemorySize,
                       (int)ATTN_SMEM);

  dim3 gb(C_MODEL / 128, T_SEQ / 128);  // (8, 32)
  gemm_bias<<<gb, 256>>>(x, Wq, bq, qp, T_SEQ, C_MODEL, C_MODEL);
  gemm_bias<<<gb, 256>>>(x, Wk, bk, kp, T_SEQ, C_MODEL, C_MODEL);
  gemm_bias<<<gb, 256>>>(x, Wv, bv, vp, T_SEQ, C_MODEL, C_MODEL);

  dim3 ga(T_SEQ / BM, NHEADS);          // (32, 16)
  flash_attn2<<<ga, 256, ATTN_SMEM>>>(qp, kp, vp, ap);

  gemm_bias<<<gb, 256>>>(ap, Wo, bo, out, T_SEQ, C_MODEL, C_MODEL);
}